// round 4
// baseline (speedup 1.0000x reference)
#include <cuda_runtime.h>

// HybridSurvivalQ: q_out = prod_{q=1..6} cos(x_q[q]+theta[q]); then 65->32->16->1
// MLP with ReLU. R=2 rows/thread, 4 CTAs/SM (regs<=128), grid=512 fits in ONE
// resident wave (<= 148*4). Weights broadcast from SMEM via LDS.128; packed
// fma.rn.f32x2 math.

#define TPB 128
#define R   2

typedef unsigned long long u64;

__device__ __forceinline__ u64 pack2(float lo, float hi) {
    u64 r;
    asm("mov.b64 %0, {%1, %2};" : "=l"(r) : "f"(lo), "f"(hi));
    return r;
}
__device__ __forceinline__ void unpack2(u64 v, float& lo, float& hi) {
    asm("mov.b64 {%0, %1}, %2;" : "=f"(lo), "=f"(hi) : "l"(v));
}
__device__ __forceinline__ u64 ffma2(u64 a, u64 b, u64 c) {
    u64 d;
    asm("fma.rn.f32x2 %0, %1, %2, %3;" : "=l"(d) : "l"(a), "l"(b), "l"(c));
    return d;
}

__global__ __launch_bounds__(TPB, 4)
void hybrid_mlp_kernel(const float* __restrict__ x_q,
                       const float* __restrict__ x_c,
                       const float* __restrict__ q_params,
                       const float* __restrict__ W1,
                       const float* __restrict__ b1,
                       const float* __restrict__ W2,
                       const float* __restrict__ b2,
                       const float* __restrict__ W3,
                       const float* __restrict__ b3,
                       float* __restrict__ out,
                       int B)
{
    __shared__ __align__(16) float sW1[65 * 32];
    __shared__ __align__(16) float sW2[32 * 16];
    __shared__ __align__(16) float sW3[16];
    __shared__ __align__(16) float sB1[32];
    __shared__ __align__(16) float sB2[16];
    __shared__ float sQP[8];
    __shared__ float sB3;

    for (int i = threadIdx.x; i < 65 * 32; i += TPB) sW1[i] = W1[i];
    for (int i = threadIdx.x; i < 32 * 16; i += TPB) sW2[i] = W2[i];
    if (threadIdx.x < 16) sW3[threadIdx.x] = W3[threadIdx.x];
    if (threadIdx.x < 32) sB1[threadIdx.x] = b1[threadIdx.x];
    if (threadIdx.x < 16) sB2[threadIdx.x] = b2[threadIdx.x];
    if (threadIdx.x < 7)  sQP[threadIdx.x] = q_params[threadIdx.x];
    if (threadIdx.x == 0) sB3 = b3[0];
    __syncthreads();

    long long gtid = (long long)blockIdx.x * TPB + threadIdx.x;
    int r0 = (int)(gtid * R);
    if (r0 >= B) return;

    int row1 = (r0 + 1 < B) ? r0 + 1 : r0;   // clamped; store guarded

    // ---- quantum part: q_out = prod_{q=1..6} cos(x_q[q] + theta[q]) ----
    float qv0, qv1;
    {
        const float* xq0 = x_q + (long long)r0 * 7;
        const float* xq1 = x_q + (long long)row1 * 7;
        float p0 = 1.0f, p1 = 1.0f;
#pragma unroll
        for (int k = 1; k < 7; k++) {
            p0 *= __cosf(xq0[k] + sQP[k]);
            p1 *= __cosf(xq1[k] + sQP[k]);
        }
        qv0 = p0; qv1 = p1;
    }

    // ---- layer 1: 65 -> 32, packed accumulators, 2 rows ----
    u64 acc0[16], acc1[16];
    const u64* bb1 = (const u64*)sB1;
#pragma unroll
    for (int k = 0; k < 16; k++) { acc0[k] = bb1[k]; acc1[k] = bb1[k]; }

    {   // input feature 0 = q_out
        u64 x0 = pack2(qv0, qv0);
        u64 x1 = pack2(qv1, qv1);
        const ulonglong2* w = (const ulonglong2*)sW1;
#pragma unroll
        for (int k2 = 0; k2 < 8; k2++) {
            ulonglong2 ww = w[k2];
            acc0[2 * k2]     = ffma2(x0, ww.x, acc0[2 * k2]);
            acc1[2 * k2]     = ffma2(x1, ww.x, acc1[2 * k2]);
            acc0[2 * k2 + 1] = ffma2(x0, ww.y, acc0[2 * k2 + 1]);
            acc1[2 * k2 + 1] = ffma2(x1, ww.y, acc1[2 * k2 + 1]);
        }
    }

    const float4* xc0 = (const float4*)(x_c + (long long)r0 * 64);
    const float4* xc1 = (const float4*)(x_c + (long long)row1 * 64);

#pragma unroll 4
    for (int j4 = 0; j4 < 16; j4++) {
        float4 v0 = xc0[j4];
        float4 v1 = xc1[j4];
        float a0[4] = {v0.x, v0.y, v0.z, v0.w};
        float a1[4] = {v1.x, v1.y, v1.z, v1.w};
#pragma unroll
        for (int s = 0; s < 4; s++) {
            int j = 1 + j4 * 4 + s;
            u64 x0 = pack2(a0[s], a0[s]);
            u64 x1 = pack2(a1[s], a1[s]);
            const ulonglong2* w = (const ulonglong2*)(sW1 + j * 32);
#pragma unroll
            for (int k2 = 0; k2 < 8; k2++) {
                ulonglong2 ww = w[k2];
                acc0[2 * k2]     = ffma2(x0, ww.x, acc0[2 * k2]);
                acc1[2 * k2]     = ffma2(x1, ww.x, acc1[2 * k2]);
                acc0[2 * k2 + 1] = ffma2(x0, ww.y, acc0[2 * k2 + 1]);
                acc1[2 * k2 + 1] = ffma2(x1, ww.y, acc1[2 * k2 + 1]);
            }
        }
    }

    // ---- relu + layer 2: 32 -> 16 (read relu'd halves straight from acc) ----
    u64 a20[8], a21[8];
    const u64* bb2 = (const u64*)sB2;
#pragma unroll
    for (int k = 0; k < 8; k++) { a20[k] = bb2[k]; a21[k] = bb2[k]; }

#pragma unroll
    for (int j = 0; j < 32; j++) {
        float lo, hi, h;
        unpack2(acc0[j >> 1], lo, hi);
        h = fmaxf((j & 1) ? hi : lo, 0.0f);
        u64 x0 = pack2(h, h);
        unpack2(acc1[j >> 1], lo, hi);
        h = fmaxf((j & 1) ? hi : lo, 0.0f);
        u64 x1 = pack2(h, h);

        const ulonglong2* w = (const ulonglong2*)(sW2 + j * 16);
#pragma unroll
        for (int k2 = 0; k2 < 4; k2++) {
            ulonglong2 ww = w[k2];
            a20[2 * k2]     = ffma2(x0, ww.x, a20[2 * k2]);
            a21[2 * k2]     = ffma2(x1, ww.x, a21[2 * k2]);
            a20[2 * k2 + 1] = ffma2(x0, ww.y, a20[2 * k2 + 1]);
            a21[2 * k2 + 1] = ffma2(x1, ww.y, a21[2 * k2 + 1]);
        }
    }

    // ---- relu + layer 3: 16 -> 1 ----
    float s0 = sB3, s1 = sB3;
#pragma unroll
    for (int k = 0; k < 8; k++) {
        float w0 = sW3[2 * k], w1 = sW3[2 * k + 1];
        float lo, hi;
        unpack2(a20[k], lo, hi);
        s0 += fmaxf(lo, 0.0f) * w0 + fmaxf(hi, 0.0f) * w1;
        unpack2(a21[k], lo, hi);
        s1 += fmaxf(lo, 0.0f) * w0 + fmaxf(hi, 0.0f) * w1;
    }

    out[r0] = s0;
    if (r0 + 1 < B) out[r0 + 1] = s1;
}

extern "C" void kernel_launch(void* const* d_in, const int* in_sizes, int n_in,
                              void* d_out, int out_size)
{
    const float* x_q      = (const float*)d_in[0];
    const float* x_c      = (const float*)d_in[1];
    const float* q_params = (const float*)d_in[2];
    const float* W1       = (const float*)d_in[3];
    const float* b1       = (const float*)d_in[4];
    const float* W2       = (const float*)d_in[5];
    const float* b2       = (const float*)d_in[6];
    const float* W3       = (const float*)d_in[7];
    const float* b3       = (const float*)d_in[8];
    float* out = (float*)d_out;

    int B = in_sizes[0] / 7;                 // x_q is (B, 7)
    long long rows_per_blk = (long long)TPB * R;
    int grid = (int)((B + rows_per_blk - 1) / rows_per_blk);

    hybrid_mlp_kernel<<<grid, TPB>>>(x_q, x_c, q_params, W1, b1, W2, b2, W3, b3,
                                     out, B);
}